// round 6
// baseline (speedup 1.0000x reference)
#include <cuda_runtime.h>
#include <cuda_pipeline.h>
#include <mma.h>

using namespace nvcuda;

#define NN 100000
#define NP 100096              // 782 * 128, padded rows for unguarded GEMM stores
#define EE 1600000
#define DD 128
#define ET (EE + NN)

// ---------------- scratch (static device globals; no allocations) ----------
__device__ int   g_flag;           // nonzero => edge_index is int32
__device__ int   g_deg[NN];        // degree over row incl. self loop
__device__ int   g_cnt[NN];        // in-degree over col incl. self loop
__device__ int   g_off[NN + 1];    // CSR offsets by col
__device__ int   g_cur[NN];        // fill cursors
__device__ float g_dis[NN];        // deg^-0.5
__device__ float g_s[NN];          // s_i = sum_j norm_ij (for bias folding)
__device__ int2  g_edges[ET];      // (src, weight-as-bits), grouped by dst
__device__ float g_P[(size_t)NP * DD];  // projected features (GEMM out, pull in)
__device__ float g_H[(size_t)NN * DD];  // hidden features (pull out, GEMM in)

__device__ __forceinline__ int ld_idx(const void* ei, long long pos, bool is32) {
    return is32 ? ((const int*)ei)[pos] : (int)((const long long*)ei)[pos];
}

// ---------------- init + dtype detect ---------------------------------------
// Block 0 additionally detects int32-vs-int64: for int64 all high words are 0.
__global__ void k_init(const int* __restrict__ ei32) {
    int i = blockIdx.x * blockDim.x + threadIdx.x;
    if (i < NN) { g_deg[i] = 1; g_cnt[i] = 1; g_cur[i] = 0; g_s[i] = 0.f; }
    if (blockIdx.x == 0) {
        __shared__ int sred[256];
        int t = threadIdx.x;
        int w = 0;
        for (int j = t; j < 4096; j += 256) w |= ei32[2 * j + 1];
        sred[t] = w;
        __syncthreads();
        for (int d = 128; d > 0; d >>= 1) {
            if (t < d) sred[t] |= sred[t + d];
            __syncthreads();
        }
        if (t == 0) g_flag = (sred[0] != 0) ? 1 : 0;
    }
}

__global__ void k_count(const void* __restrict__ ei) {
    int e = blockIdx.x * blockDim.x + threadIdx.x;
    bool is32 = (g_flag != 0);
    if (e < EE) {
        int r = ld_idx(ei, e, is32);
        int c = ld_idx(ei, (long long)EE + e, is32);
        if ((unsigned)r < NN && (unsigned)c < NN) {
            atomicAdd(&g_deg[r], 1);   // row (source)
            atomicAdd(&g_cnt[c], 1);   // col (target)
        }
    }
}

// exclusive scan of g_cnt -> g_off, plus g_dis = deg^-0.5; one block of 1024
__global__ __launch_bounds__(1024) void k_scan() {
    const int T = 1024;
    const int C = (NN + T - 1) / T;   // 98
    int t = threadIdx.x;
    int base = t * C;
    int s = 0;
    for (int j = 0; j < C; j++) {
        int idx = base + j;
        if (idx < NN) {
            s += g_cnt[idx];
            g_dis[idx] = rsqrtf((float)g_deg[idx]);
        }
    }
    __shared__ int ps[T];
    ps[t] = s;
    __syncthreads();
    for (int d = 1; d < T; d <<= 1) {
        int v = (t >= d) ? ps[t - d] : 0;
        __syncthreads();
        ps[t] += v;
        __syncthreads();
    }
    int run = ps[t] - s;  // exclusive prefix
    for (int j = 0; j < C; j++) {
        int idx = base + j;
        if (idx < NN) { g_off[idx] = run; run += g_cnt[idx]; }
    }
    if (t == T - 1) g_off[NN] = run;
}

// scatter edges (and self loops) into CSR-by-col with fused weights;
// also accumulate s_i = sum of weights per target (bias folding).
__global__ void k_fill(const void* __restrict__ ei) {
    int e = blockIdx.x * blockDim.x + threadIdx.x;
    bool is32 = (g_flag != 0);
    if (e < EE) {
        int r = ld_idx(ei, e, is32);
        int c = ld_idx(ei, (long long)EE + e, is32);
        if ((unsigned)r < NN && (unsigned)c < NN) {
            float w = g_dis[r] * g_dis[c];
            int pos = g_off[c] + atomicAdd(&g_cur[c], 1);
            g_edges[pos] = make_int2(r, __float_as_int(w));
            atomicAdd(&g_s[c], w);
        }
    } else if (e < ET) {
        int i = e - EE;
        float d = g_dis[i];
        float w = d * d;
        int pos = g_off[i] + atomicAdd(&g_cur[i], 1);
        g_edges[pos] = make_int2(i, __float_as_int(w));
        atomicAdd(&g_s[i], w);
    }
}

// ---------------- GEMM: g_P[N,128] = A[N,128] @ W^T  (no bias) -------------
// 3xTF32 with register-side hi/lo split, f32 tiles in smem, cp.async 2-stage.
// Block 128x128, BK=16, 8 warps: warp_m = w&1 (64 rows), warp_n = w>>1 (32 cols).
__device__ __forceinline__ float tf32_hi(float x) {
    return __uint_as_float(__float_as_uint(x) & 0xFFFFE000u);
}

#define LDK 24   // padded row length (floats); 96B rows, 32B-aligned frag ptrs

template <bool USE_H>
__global__ __launch_bounds__(256) void k_gemm(const float* __restrict__ Ax,
                                              const float* __restrict__ Wm) {
    __shared__ __align__(32) float sA[2][128 * LDK];
    __shared__ __align__(32) float sW[2][128 * LDK];

    const float* __restrict__ A = USE_H ? (const float*)g_H : Ax;

    int t = threadIdx.x;
    int w = t >> 5;
    int warp_m = w & 1;      // rows warp_m*64 .. +63
    int warp_n = w >> 1;     // cols warp_n*32 .. +31
    int rowBase = blockIdx.x * 128;

    wmma::fragment<wmma::accumulator, 16, 16, 8, float> acc[4][2];
#pragma unroll
    for (int i = 0; i < 4; i++)
#pragma unroll
        for (int j = 0; j < 2; j++) wmma::fill_fragment(acc[i][j], 0.f);

    // async tile loaders: 512 16B-chunks per tile, 2 per thread per tile
    auto load_stage = [&](int kt, int buf) {
#pragma unroll
        for (int i = 0; i < 2; i++) {
            int idx = t + i * 256;        // 0..511
            int r = idx >> 2, c4 = idx & 3;
            int gr = rowBase + r; if (gr >= NN) gr = NN - 1;   // clamp
            __pipeline_memcpy_async(&sA[buf][r * LDK + c4 * 4],
                                    A + (size_t)gr * DD + kt * 16 + c4 * 4, 16);
        }
#pragma unroll
        for (int i = 0; i < 2; i++) {
            int idx = t + i * 256;
            int r = idx >> 2, c4 = idx & 3;
            __pipeline_memcpy_async(&sW[buf][r * LDK + c4 * 4],
                                    Wm + (size_t)r * DD + kt * 16 + c4 * 4, 16);
        }
    };

    load_stage(0, 0);
    __pipeline_commit();

    for (int kt = 0; kt < 8; kt++) {
        if (kt < 7) { load_stage(kt + 1, (kt + 1) & 1); __pipeline_commit(); }
        if (kt < 7) __pipeline_wait_prior(1);
        else        __pipeline_wait_prior(0);
        __syncthreads();

        int buf = kt & 1;
#pragma unroll
        for (int ks = 0; ks < 2; ks++) {
            int k0 = ks * 8;
            // load raw f32 fragments, split hi/lo in registers
            wmma::fragment<wmma::matrix_a, 16, 16, 8, wmma::precision::tf32, wmma::row_major> ar, ahi, alo;
            wmma::fragment<wmma::matrix_b, 16, 16, 8, wmma::precision::tf32, wmma::col_major> br, bhi, blo;
            wmma::fragment<wmma::matrix_a, 16, 16, 8, wmma::precision::tf32, wmma::row_major> Ahi[4], Alo[4];
#pragma unroll
            for (int i = 0; i < 4; i++) {
                wmma::load_matrix_sync(ar, &sA[buf][(warp_m * 64 + i * 16) * LDK + k0], LDK);
#pragma unroll
                for (int x = 0; x < ar.num_elements; x++) {
                    float h = tf32_hi(ar.x[x]);
                    Ahi[i].x[x] = h;
                    Alo[i].x[x] = ar.x[x] - h;
                }
            }
#pragma unroll
            for (int j = 0; j < 2; j++) {
                wmma::load_matrix_sync(br, &sW[buf][(warp_n * 32 + j * 16) * LDK + k0], LDK);
#pragma unroll
                for (int x = 0; x < br.num_elements; x++) {
                    float h = tf32_hi(br.x[x]);
                    bhi.x[x] = h;
                    blo.x[x] = br.x[x] - h;
                }
#pragma unroll
                for (int i = 0; i < 4; i++) {
                    wmma::mma_sync(acc[i][j], Ahi[i], bhi, acc[i][j]);
                    wmma::mma_sync(acc[i][j], Alo[i], bhi, acc[i][j]);
                    wmma::mma_sync(acc[i][j], Ahi[i], blo, acc[i][j]);
                }
            }
        }
        __syncthreads();
    }

    // store raw accumulators (g_P padded to NP rows -> no guard needed)
#pragma unroll
    for (int i = 0; i < 4; i++)
#pragma unroll
        for (int j = 0; j < 2; j++) {
            float* out = g_P + (size_t)(rowBase + warp_m * 64 + i * 16) * DD
                       + warp_n * 32 + j * 16;
            wmma::store_matrix_sync(out, acc[i][j], DD, wmma::mem_row_major);
        }
}

// ---------------- pull aggregation + bias + ReLU ----------------------------
// one warp per node; lane owns cols lane*4..+3 (float4). Reads g_P.
// out_i = relu( sum_j w_ij * p_j  +  b * s_i )
template <bool TO_H>
__global__ __launch_bounds__(256) void k_pull(const float* __restrict__ bias,
                                              float* __restrict__ Ox) {
    int gw = (blockIdx.x * blockDim.x + threadIdx.x) >> 5;
    int lane = threadIdx.x & 31;
    if (gw >= NN) return;
    int s = g_off[gw];
    int e = g_off[gw + 1];
    const float4* __restrict__ Pb = (const float4*)g_P;
    float4 acc = make_float4(0.f, 0.f, 0.f, 0.f);
    int j = s;
    for (; j + 2 <= e; j += 2) {
        int2 e0 = g_edges[j];
        int2 e1 = g_edges[j + 1];
        float4 v0 = Pb[(size_t)e0.x * 32 + lane];
        float4 v1 = Pb[(size_t)e1.x * 32 + lane];
        float w0 = __int_as_float(e0.y);
        float w1 = __int_as_float(e1.y);
        acc.x += w0 * v0.x + w1 * v1.x;
        acc.y += w0 * v0.y + w1 * v1.y;
        acc.z += w0 * v0.z + w1 * v1.z;
        acc.w += w0 * v0.w + w1 * v1.w;
    }
    if (j < e) {
        int2 e0 = g_edges[j];
        float4 v0 = Pb[(size_t)e0.x * 32 + lane];
        float w0 = __int_as_float(e0.y);
        acc.x += w0 * v0.x;
        acc.y += w0 * v0.y;
        acc.z += w0 * v0.z;
        acc.w += w0 * v0.w;
    }
    float si = g_s[gw];
    float4 b4 = *(const float4*)(bias + lane * 4);
    float4 r = make_float4(fmaxf(acc.x + b4.x * si, 0.f),
                           fmaxf(acc.y + b4.y * si, 0.f),
                           fmaxf(acc.z + b4.z * si, 0.f),
                           fmaxf(acc.w + b4.w * si, 0.f));
    float4* Ob = TO_H ? (float4*)g_H : (float4*)Ox;
    Ob[(size_t)gw * 32 + lane] = r;
}

// ---------------- launch ----------------------------------------------------
extern "C" void kernel_launch(void* const* d_in, const int* in_sizes, int n_in,
                              void* d_out, int out_size) {
    const float* x  = (const float*)d_in[0];
    const void*  ei = d_in[1];                 // int32 or int64, detected on device
    const float* W1 = (const float*)d_in[2];
    const float* b1 = (const float*)d_in[3];
    const float* W2 = (const float*)d_in[4];
    const float* b2 = (const float*)d_in[5];
    const float* W3 = (const float*)d_in[6];
    const float* b3 = (const float*)d_in[7];
    float* out = (float*)d_out;

    const int TB = 256;
    // preprocess (4 launches)
    k_init <<<(NP + TB - 1) / TB, TB>>>((const int*)ei);
    k_count<<<(EE + TB - 1) / TB, TB>>>(ei);
    k_scan <<<1, 1024>>>();
    k_fill <<<(ET + TB - 1) / TB, TB>>>(ei);

    const int GB = (NN + 127) / 128;          // gemm blocks (782)
    const int PB = (NN * 32 + TB - 1) / TB;   // pull blocks (warp per node)

    // layer 1: x -> P -> H
    k_gemm<false><<<GB, 256>>>(x, W1);
    k_pull<true><<<PB, 256>>>(b1, nullptr);
    // layer 2: H -> P -> H
    k_gemm<true><<<GB, 256>>>(nullptr, W2);
    k_pull<true><<<PB, 256>>>(b2, nullptr);
    // layer 3: H -> P -> out
    k_gemm<true><<<GB, 256>>>(nullptr, W3);
    k_pull<false><<<PB, 256>>>(b3, out);
}